// round 3
// baseline (speedup 1.0000x reference)
#include <cuda_runtime.h>

// QSP expectation, single fused kernel.
//
// g(theta) = Re( e^{i phi0} P00(theta) ) is an exact trig polynomial:
//   g = sum_{j=0..27} A_j cos(2 j theta) + B_j sin(2 j theta)
// Block 0 samples the 54-step unitary chain at theta_k = pi k/64 and extracts
// A_j, B_j by exact 64-point DFT (table-based), publishes them with a
// release flag. All blocks spin-acquire, then evaluate the series with two
// f32x2-packed Clenshaw pairs (4 elements/thread, 4 independent chains).
// Flag + done-counter are reset by the last block => deterministic per call.

#define NSTEP 54
#define NHARM 27
#define NSAMP 64

typedef unsigned long long u64;

__device__ float g_coefA[32];           // A_0..A_27
__device__ float g_coefB[32];           // B_1..B_27 (B_0 stays 0)
__device__ unsigned int g_flag = 0;
__device__ unsigned int g_done = 0;

__device__ __forceinline__ u64 pk2(float lo, float hi) {
    u64 r; asm("mov.b64 %0, {%1, %2};" : "=l"(r) : "f"(lo), "f"(hi)); return r;
}
__device__ __forceinline__ void upk2(u64 v, float& lo, float& hi) {
    asm("mov.b64 {%0, %1}, %2;" : "=f"(lo), "=f"(hi) : "l"(v));
}
__device__ __forceinline__ u64 fma2(u64 a, u64 b, u64 c) {
    u64 d; asm("fma.rn.f32x2 %0, %1, %2, %3;" : "=l"(d) : "l"(a), "l"(b), "l"(c)); return d;
}
__device__ __forceinline__ u64 sub2(u64 a, u64 b) {
    u64 d; asm("sub.rn.f32x2 %0, %1, %2;" : "=l"(d) : "l"(a), "l"(b)); return d;
}

__global__ void __launch_bounds__(256, 4)
qsp_fused(const float2* __restrict__ x2,
          const float*  __restrict__ phis,
          const float2* __restrict__ a2,
          const float*  __restrict__ bias,
          float2* __restrict__ out2,
          int th_total)                 // total threads = n/4
{
    __shared__ float pc[NSTEP], ps[NSTEP];
    __shared__ float gs[NSAMP];
    __shared__ float tab[NSAMP];
    __shared__ u64 sA[NHARM + 1], sB[NHARM + 1];

    const int t = threadIdx.x;

    if (blockIdx.x == 0) {
        // ---- coefficient precompute (block 0 only) ----
        if (t < NSTEP) {
            float sp, cp; sincosf(phis[t + 1], &sp, &cp);
            pc[t] = cp; ps[t] = sp;
        }
        if (t < NSAMP) tab[t] = sinpif((float)t * (1.0f / 32.0f));
        __syncthreads();

        if (t < NSAMP) {
            float s, c; sincospif((float)t * (1.0f / 64.0f), &s, &c);
            float x0 = 1.0f, y0 = 0.0f, x1 = 0.0f, y1 = 0.0f;
            #pragma unroll
            for (int k = 0; k < NSTEP; ++k) {
                const float ec = pc[k], es = ps[k];
                const float ux = c * x0 - s * y1;
                const float uy = c * y0 + s * x1;
                const float vx = c * x1 - s * y0;
                const float vy = c * y1 + s * x0;
                x0 = ec * ux - es * uy;
                y0 = es * ux + ec * uy;
                x1 = ec * vx + es * vy;
                y1 = ec * vy - es * vx;
            }
            float s0, c0; sincosf(phis[0], &s0, &c0);
            gs[t] = c0 * x0 - s0 * y0;
        }
        __syncthreads();

        // exact DFT via shared sinpi table: cos(pi*m/32) = tab[(m+16)&63]
        if (t <= NHARM) {
            float a0 = 0.f, a1 = 0.f, a2s = 0.f, a3 = 0.f;
            #pragma unroll
            for (int k = 0; k < NSAMP; k += 4) {
                a0  = fmaf(gs[k+0], tab[(t*(k+0) + 16) & 63], a0);
                a1  = fmaf(gs[k+1], tab[(t*(k+1) + 16) & 63], a1);
                a2s = fmaf(gs[k+2], tab[(t*(k+2) + 16) & 63], a2s);
                a3  = fmaf(gs[k+3], tab[(t*(k+3) + 16) & 63], a3);
            }
            const float acc = (a0 + a1) + (a2s + a3);
            g_coefA[t] = acc * ((t == 0) ? (1.0f / 64.0f) : (2.0f / 64.0f));
        } else if (t >= 32 && t <= 31 + NHARM) {
            const int j = t - 31;
            float a0 = 0.f, a1 = 0.f, a2s = 0.f, a3 = 0.f;
            #pragma unroll
            for (int k = 0; k < NSAMP; k += 4) {
                a0  = fmaf(gs[k+0], tab[(j*(k+0)) & 63], a0);
                a1  = fmaf(gs[k+1], tab[(j*(k+1)) & 63], a1);
                a2s = fmaf(gs[k+2], tab[(j*(k+2)) & 63], a2s);
                a3  = fmaf(gs[k+3], tab[(j*(k+3)) & 63], a3);
            }
            g_coefB[j] = ((a0 + a1) + (a2s + a3)) * (2.0f / 64.0f);
        }
        __syncthreads();
        if (t == 0) {
            __threadfence();
            atomicExch(&g_flag, 1u);
        }
    } else {
        // ---- consumers: spin until coefficients are published ----
        if (t == 0) {
            unsigned f;
            do {
                asm volatile("ld.acquire.gpu.b32 %0, [%1];"
                             : "=r"(f) : "l"(&g_flag) : "memory");
                if (!f) __nanosleep(64);
            } while (!f);
        }
        __syncthreads();
    }

    // ---- broadcast coefficients into shared, packed for f32x2 ----
    if (t <= NHARM) { const float a = g_coefA[t]; sA[t] = pk2(a, a); }
    if (t >= 64 && t <= 64 + NHARM) {
        const int j = t - 64;
        const float b = g_coefB[j]; sB[j] = pk2(b, b);
    }
    __syncthreads();

    // ---- evaluation: 4 elements per thread, two packed Clenshaw pairs ----
    const int T = blockIdx.x * blockDim.x + t;
    if (T < th_total) {
        const float2 xa = x2[T];
        const float2 xb = x2[T + th_total];

        float s0, c0, s1, c1, s2, c2, s3, c3;
        __sincosf(2.0f * xa.x, &s0, &c0);
        __sincosf(2.0f * xa.y, &s1, &c1);
        __sincosf(2.0f * xb.x, &s2, &c2);
        __sincosf(2.0f * xb.y, &s3, &c3);

        const u64 twA = pk2(2.0f * c0, 2.0f * c1);
        const u64 twB = pk2(2.0f * c2, 2.0f * c3);
        const u64 cuA = pk2(c0, c1), suA = pk2(s0, s1);
        const u64 cuB = pk2(c2, c3), suB = pk2(s2, s3);

        u64 b1A = 0, b2A = 0, d1A = 0, d2A = 0;
        u64 b1B = 0, b2B = 0, d1B = 0, d2B = 0;

        #pragma unroll
        for (int k = NHARM; k >= 1; --k) {
            const u64 Ak = sA[k], Bk = sB[k];
            u64 nb;
            nb = fma2(twA, b1A, sub2(Ak, b2A)); b2A = b1A; b1A = nb;
            nb = fma2(twA, d1A, sub2(Bk, d2A)); d2A = d1A; d1A = nb;
            nb = fma2(twB, b1B, sub2(Ak, b2B)); b2B = b1B; b1B = nb;
            nb = fma2(twB, d1B, sub2(Bk, d2B)); d2B = d1B; d1B = nb;
        }

        const u64 A0 = sA[0];
        u64 fA = sub2(A0, b2A);
        fA = fma2(cuA, b1A, fA);
        fA = fma2(suA, d1A, fA);
        u64 fB = sub2(A0, b2B);
        fB = fma2(cuB, b1B, fB);
        fB = fma2(suB, d1B, fB);

        float f0, f1, f2, f3;
        upk2(fA, f0, f1);
        upk2(fB, f2, f3);

        const float bb = bias[0];
        const float2 aa = a2[T];
        const float2 ab = a2[T + th_total];
        out2[T]            = make_float2(fmaf(aa.x, f0, bb), fmaf(aa.y, f1, bb));
        out2[T + th_total] = make_float2(fmaf(ab.x, f2, bb), fmaf(ab.y, f3, bb));
    }

    // ---- reset flag for next invocation (last block) ----
    __syncthreads();
    if (t == 0) {
        __threadfence();
        const unsigned r = atomicAdd(&g_done, 1u);
        if (r == gridDim.x - 1) {
            g_done = 0;
            atomicExch(&g_flag, 0u);
        }
    }
}

// ---------------------------------------------------------------------------
// Fallback for unexpected shapes (direct chain evaluation).
// ---------------------------------------------------------------------------
__global__ void __launch_bounds__(256)
qsp_generic(const float* __restrict__ x,
            const float* __restrict__ phis,
            const float* __restrict__ alphas,
            const float* __restrict__ bias,
            float* __restrict__ out,
            int n, int nsteps)
{
    __shared__ float pc[256], ps[256];
    __shared__ float s0c, s0s;
    int t = threadIdx.x;
    if (t < nsteps && t < 256) {
        float sp, cp; sincosf(phis[t + 1], &sp, &cp);
        pc[t] = cp; ps[t] = sp;
    }
    if (t == 0) {
        float sp, cp; sincosf(phis[0], &sp, &cp);
        s0c = cp; s0s = sp;
    }
    __syncthreads();

    const int i = blockIdx.x * blockDim.x + t;
    if (i >= n) return;

    float s, c; sincosf(x[i], &s, &c);
    float x0 = 1.0f, y0 = 0.0f, x1 = 0.0f, y1 = 0.0f;
    for (int k = 0; k < nsteps; ++k) {
        const float ec = (k < 256) ? pc[k] : cosf(phis[k + 1]);
        const float es = (k < 256) ? ps[k] : sinf(phis[k + 1]);
        const float ux = c * x0 - s * y1;
        const float uy = c * y0 + s * x1;
        const float vx = c * x1 - s * y0;
        const float vy = c * y1 + s * x0;
        x0 = ec * ux - es * uy;
        y0 = es * ux + ec * uy;
        x1 = ec * vx + es * vy;
        y1 = ec * vy - es * vx;
    }
    const float re = s0c * x0 - s0s * y0;
    out[i] = fmaf(alphas[i], re, bias[0]);
}

extern "C" void kernel_launch(void* const* d_in, const int* in_sizes, int n_in,
                              void* d_out, int out_size)
{
    const float* x      = (const float*)d_in[0];
    const float* phis   = (const float*)d_in[1];
    const float* alphas = (const float*)d_in[2];
    const float* bias   = (const float*)d_in[3];
    float* out = (float*)d_out;

    const int n      = in_sizes[0];
    const int nph    = in_sizes[1];
    const int nsteps = nph - 1;

    if (nsteps == NSTEP && (n & 3) == 0) {
        const int th_total = n >> 2;               // 4 elems / thread
        const int threads  = 256;
        const int blocks   = (th_total + threads - 1) / threads;
        qsp_fused<<<blocks, threads>>>((const float2*)x, phis,
                                       (const float2*)alphas, bias,
                                       (float2*)out, th_total);
    } else {
        const int threads = 256;
        const int blocks  = (n + threads - 1) / threads;
        qsp_generic<<<blocks, threads>>>(x, phis, alphas, bias, out, n, nsteps);
    }
}

// round 4
// speedup vs baseline: 1.4571x; 1.4571x over previous
#include <cuda_runtime.h>

// QSP expectation, single fused kernel, ZERO inter-block communication.
//
// g(theta) = Re( e^{i phi0} P00(theta) ) is an exact trig polynomial:
//   g = sum_{j=0..27} A_j cos(2 j theta) + B_j sin(2 j theta)
// EVERY block redundantly (a) samples the 54-step chain at theta_k = pi k/64
// (64 threads), (b) extracts A_j, B_j via an exact table-based 64-point DFT
// (55 threads), then (c) all 1024 threads evaluate the series with two
// f32x2-packed Clenshaw pairs (4 elements/thread). No atomics, no flags.

#define NSTEP 54
#define NHARM 27
#define NSAMP 64

typedef unsigned long long u64;

__device__ __forceinline__ u64 pk2(float lo, float hi) {
    u64 r; asm("mov.b64 %0, {%1, %2};" : "=l"(r) : "f"(lo), "f"(hi)); return r;
}
__device__ __forceinline__ void upk2(u64 v, float& lo, float& hi) {
    asm("mov.b64 {%0, %1}, %2;" : "=f"(lo), "=f"(hi) : "l"(v));
}
__device__ __forceinline__ u64 fma2(u64 a, u64 b, u64 c) {
    u64 d; asm("fma.rn.f32x2 %0, %1, %2, %3;" : "=l"(d) : "l"(a), "l"(b), "l"(c)); return d;
}
__device__ __forceinline__ u64 sub2(u64 a, u64 b) {
    u64 d; asm("sub.rn.f32x2 %0, %1, %2;" : "=l"(d) : "l"(a), "l"(b)); return d;
}

__global__ void __launch_bounds__(1024, 1)
qsp_fused(const float4* __restrict__ x4,
          const float*  __restrict__ phis,
          const float4* __restrict__ a4,
          const float*  __restrict__ bias,
          float4* __restrict__ out4,
          int nq)                       // nq = n/4
{
    __shared__ float pc[NSTEP], ps[NSTEP];
    __shared__ float gs[NSAMP];
    __shared__ float tab[NSAMP];
    __shared__ u64 sA[NHARM + 1], sB[NHARM + 1];

    const int t = threadIdx.x;

    // ---- per-block coefficient precompute (redundant, cheap) ----
    if (t < NSTEP) {
        float sp, cp; sincosf(phis[t + 1], &sp, &cp);   // accurate (error-critical)
        pc[t] = cp; ps[t] = sp;
    }
    if (t >= 64 && t < 64 + NSAMP) {
        const int i = t - 64;
        tab[i] = sinpif((float)i * (1.0f / 32.0f));     // sin(pi*i/32), period 64
    }
    __syncthreads();

    if (t < NSAMP) {
        // chain at theta = pi * t / 64 (row 0 of the product only)
        float s, c; sincospif((float)t * (1.0f / 64.0f), &s, &c);
        float x0 = 1.0f, y0 = 0.0f, x1 = 0.0f, y1 = 0.0f;
        #pragma unroll
        for (int k = 0; k < NSTEP; ++k) {
            const float ec = pc[k], es = ps[k];
            const float ux = c * x0 - s * y1;
            const float uy = c * y0 + s * x1;
            const float vx = c * x1 - s * y0;
            const float vy = c * y1 + s * x0;
            x0 = ec * ux - es * uy;
            y0 = es * ux + ec * uy;
            x1 = ec * vx + es * vy;
            y1 = ec * vy - es * vx;
        }
        float s0, c0; sincosf(phis[0], &s0, &c0);
        gs[t] = c0 * x0 - s0 * y0;
    }
    __syncthreads();

    // exact 64-point DFT via table: cos(pi*m/32) = tab[(m+16)&63]
    if (t <= NHARM) {
        float a0 = 0.f, a1 = 0.f, a2s = 0.f, a3 = 0.f;
        #pragma unroll
        for (int k = 0; k < NSAMP; k += 4) {
            a0  = fmaf(gs[k+0], tab[(t*(k+0) + 16) & 63], a0);
            a1  = fmaf(gs[k+1], tab[(t*(k+1) + 16) & 63], a1);
            a2s = fmaf(gs[k+2], tab[(t*(k+2) + 16) & 63], a2s);
            a3  = fmaf(gs[k+3], tab[(t*(k+3) + 16) & 63], a3);
        }
        const float v = ((a0 + a1) + (a2s + a3)) *
                        ((t == 0) ? (1.0f / 64.0f) : (2.0f / 64.0f));
        sA[t] = pk2(v, v);
    } else if (t >= 32 && t <= 31 + NHARM) {
        const int j = t - 31;   // 1..27
        float a0 = 0.f, a1 = 0.f, a2s = 0.f, a3 = 0.f;
        #pragma unroll
        for (int k = 0; k < NSAMP; k += 4) {
            a0  = fmaf(gs[k+0], tab[(j*(k+0)) & 63], a0);
            a1  = fmaf(gs[k+1], tab[(j*(k+1)) & 63], a1);
            a2s = fmaf(gs[k+2], tab[(j*(k+2)) & 63], a2s);
            a3  = fmaf(gs[k+3], tab[(j*(k+3)) & 63], a3);
        }
        const float v = ((a0 + a1) + (a2s + a3)) * (2.0f / 64.0f);
        sB[j] = pk2(v, v);
    }
    __syncthreads();

    // ---- evaluation: 4 elements per thread, two packed Clenshaw pairs ----
    const int T = blockIdx.x * blockDim.x + t;
    if (T >= nq) return;

    const float4 xv = x4[T];
    float s0, c0, s1, c1, s2, c2, s3, c3;
    __sincosf(2.0f * xv.x, &s0, &c0);
    __sincosf(2.0f * xv.y, &s1, &c1);
    __sincosf(2.0f * xv.z, &s2, &c2);
    __sincosf(2.0f * xv.w, &s3, &c3);

    const u64 twA = pk2(2.0f * c0, 2.0f * c1);
    const u64 twB = pk2(2.0f * c2, 2.0f * c3);
    const u64 cuA = pk2(c0, c1), suA = pk2(s0, s1);
    const u64 cuB = pk2(c2, c3), suB = pk2(s2, s3);

    u64 b1A = 0, b2A = 0, d1A = 0, d2A = 0;
    u64 b1B = 0, b2B = 0, d1B = 0, d2B = 0;

    #pragma unroll
    for (int k = NHARM; k >= 1; --k) {
        const u64 Ak = sA[k], Bk = sB[k];
        u64 nb;
        nb = fma2(twA, b1A, sub2(Ak, b2A)); b2A = b1A; b1A = nb;
        nb = fma2(twA, d1A, sub2(Bk, d2A)); d2A = d1A; d1A = nb;
        nb = fma2(twB, b1B, sub2(Ak, b2B)); b2B = b1B; b1B = nb;
        nb = fma2(twB, d1B, sub2(Bk, d2B)); d2B = d1B; d1B = nb;
    }

    const u64 A0 = sA[0];
    u64 fA = sub2(A0, b2A);
    fA = fma2(cuA, b1A, fA);
    fA = fma2(suA, d1A, fA);
    u64 fB = sub2(A0, b2B);
    fB = fma2(cuB, b1B, fB);
    fB = fma2(suB, d1B, fB);

    float f0, f1, f2, f3;
    upk2(fA, f0, f1);
    upk2(fB, f2, f3);

    const float bb = bias[0];
    const float4 av = a4[T];
    out4[T] = make_float4(fmaf(av.x, f0, bb), fmaf(av.y, f1, bb),
                          fmaf(av.z, f2, bb), fmaf(av.w, f3, bb));
}

// ---------------------------------------------------------------------------
// Fallback for unexpected shapes (direct chain evaluation).
// ---------------------------------------------------------------------------
__global__ void __launch_bounds__(256)
qsp_generic(const float* __restrict__ x,
            const float* __restrict__ phis,
            const float* __restrict__ alphas,
            const float* __restrict__ bias,
            float* __restrict__ out,
            int n, int nsteps)
{
    __shared__ float pc[256], ps[256];
    __shared__ float s0c, s0s;
    int t = threadIdx.x;
    if (t < nsteps && t < 256) {
        float sp, cp; sincosf(phis[t + 1], &sp, &cp);
        pc[t] = cp; ps[t] = sp;
    }
    if (t == 0) {
        float sp, cp; sincosf(phis[0], &sp, &cp);
        s0c = cp; s0s = sp;
    }
    __syncthreads();

    const int i = blockIdx.x * blockDim.x + t;
    if (i >= n) return;

    float s, c; sincosf(x[i], &s, &c);
    float x0 = 1.0f, y0 = 0.0f, x1 = 0.0f, y1 = 0.0f;
    for (int k = 0; k < nsteps; ++k) {
        const float ec = (k < 256) ? pc[k] : cosf(phis[k + 1]);
        const float es = (k < 256) ? ps[k] : sinf(phis[k + 1]);
        const float ux = c * x0 - s * y1;
        const float uy = c * y0 + s * x1;
        const float vx = c * x1 - s * y0;
        const float vy = c * y1 + s * x0;
        x0 = ec * ux - es * uy;
        y0 = es * ux + ec * uy;
        x1 = ec * vx + es * vy;
        y1 = ec * vy - es * vx;
    }
    const float re = s0c * x0 - s0s * y0;
    out[i] = fmaf(alphas[i], re, bias[0]);
}

extern "C" void kernel_launch(void* const* d_in, const int* in_sizes, int n_in,
                              void* d_out, int out_size)
{
    const float* x      = (const float*)d_in[0];
    const float* phis   = (const float*)d_in[1];
    const float* alphas = (const float*)d_in[2];
    const float* bias   = (const float*)d_in[3];
    float* out = (float*)d_out;

    const int n      = in_sizes[0];
    const int nph    = in_sizes[1];
    const int nsteps = nph - 1;

    if (nsteps == NSTEP && (n & 3) == 0) {
        const int nq      = n >> 2;                 // float4 quads
        const int threads = 1024;
        const int blocks  = (nq + threads - 1) / threads;   // 128 for n=524288
        qsp_fused<<<blocks, threads>>>((const float4*)x, phis,
                                       (const float4*)alphas, bias,
                                       (float4*)out, nq);
    } else {
        const int threads = 256;
        const int blocks  = (n + threads - 1) / threads;
        qsp_generic<<<blocks, threads>>>(x, phis, alphas, bias, out, n, nsteps);
    }
}